// round 13
// baseline (speedup 1.0000x reference)
#include <cuda_runtime.h>
#include <cuda_fp16.h>
#include <math_constants.h>

#define NNODES 100000
#define NEDGES 1600000
#define HD     64
#define NCLS   10
#define NGRAPH 128
#define CAP    64     // bucket capacity per node (deg ~ Poisson(16); P(>63) ~ 1e-21)

typedef unsigned long long ull;

// packed fp32x2 FMA (Blackwell): d = a*b + d per 32-bit half. Bit-identical fp32.
#define FMA2(d, a, b) asm("fma.rn.f32x2 %0, %1, %2, %3;" : "=l"(d) : "l"(a), "l"(b), "l"(d))
#define PACK2(d, lo, hi) asm("mov.b64 %0, {%1, %2};" : "=l"(d) : "f"(lo), "f"(hi))
#define PACKDUP(d, s)    asm("mov.b64 %0, {%1, %1};" : "=l"(d) : "f"(s))
#define UNPACK2(lo, hi, s) asm("mov.b64 {%0, %1}, %2;" : "=f"(lo), "=f"(hi) : "l"(s))

// ---------------- scratch (device globals; no allocations) ----------------
__device__ __align__(16) __half2 g_h16[NNODES * 32];  // h rows, fp16 payload (128B/row)
__device__ __align__(16) float g_abuf[NNODES * HD];   // conv input / output (fp32)
__device__ float g_als[NNODES];
__device__ float g_ald[NNODES];
__device__ int   g_cursor[NNODES];                    // row length after scatter
__device__ int   g_bucket[NNODES * CAP];              // src ids, row n at n*CAP

__device__ __forceinline__ float eluf(float x) {
    return x > 0.f ? x : expm1f(x);
}

// ---------------- bucket init + out zero -----------------------------------
__global__ void k_init(float* __restrict__ out) {
    int i = blockIdx.x * blockDim.x + threadIdx.x;
    if (i < NNODES) {
        g_cursor[i] = 1;               // slot 0 = self loop
        g_bucket[i * CAP] = i;
    }
    if (i < NGRAPH * NCLS) out[i] = 0.f;
}

// ---------------- edge scatter into fixed buckets ---------------------------
// edge_index is INT32 (JAX x64 disabled downgrades jnp.int64 -> int32)
__global__ void k_scatter(const int* __restrict__ ei) {
    int i = (blockIdx.x * blockDim.x + threadIdx.x) * 4;
    if (i >= NEDGES) return;
    int4 s = *(const int4*)(ei + i);
    int4 d = *(const int4*)(ei + NEDGES + i);
    int p0 = atomicAdd(&g_cursor[d.x], 1);
    int p1 = atomicAdd(&g_cursor[d.y], 1);
    int p2 = atomicAdd(&g_cursor[d.z], 1);
    int p3 = atomicAdd(&g_cursor[d.w], 1);
    if (p0 < CAP) g_bucket[d.x * CAP + p0] = s.x;
    if (p1 < CAP) g_bucket[d.y * CAP + p1] = s.y;
    if (p2 < CAP) g_bucket[d.z * CAP + p2] = s.z;
    if (p3 < CAP) g_bucket[d.w * CAP + p3] = s.w;
}

// ---------------- GEMM + attention coefs (f32x2 packed FMA) -----------------
// Thread tile 4 rows x 4 cols. Accumulators packed along row pairs:
// acc01[c] = {r0c, r1c}, acc23[c] = {r2c, r3c}. W stored column-duplicated
// in smem so {w,w} pairs load directly; x scalars packed with one mov.b64.
template <int LAYER>
__global__ __launch_bounds__(256) void k_gemm_attn(
    const float* __restrict__ xin,
    const float* __restrict__ W,
    const float* __restrict__ a_s,
    const float* __restrict__ a_d)
{
    __shared__ __align__(16) float Wd[64 * 128];   // col-duplicated W (32KB)
    __shared__ __align__(16) float xs[64 * 64];    // x tile, row-major (16KB)

    int t = threadIdx.x;
    int base = blockIdx.x * 64;

    // load W, duplicating each column: Wd[k][2c] = Wd[k][2c+1] = W[k][c]
    for (int i = t; i < 1024; i += 256) {
        int k = i >> 4, c4 = i & 15;
        float4 w = *(const float4*)(W + k * 64 + c4 * 4);
        float4 lo = make_float4(w.x, w.x, w.y, w.y);
        float4 hi = make_float4(w.z, w.z, w.w, w.w);
        *(float4*)&Wd[k * 128 + c4 * 8]     = lo;
        *(float4*)&Wd[k * 128 + c4 * 8 + 4] = hi;
    }
    // load x tile (coalesced); ELU-on-load for layer 2; OOB rows -> 0
    for (int i = t; i < 1024; i += 256) {
        int row = i >> 4, c4 = i & 15;
        int grow = base + row;
        float4 v = make_float4(0.f, 0.f, 0.f, 0.f);
        if (grow < NNODES) {
            if (LAYER == 0) {
                v = *(const float4*)(xin + grow * 64 + c4 * 4);
            } else {
                float4 u = *(const float4*)&g_abuf[grow * 64 + c4 * 4];
                v = make_float4(eluf(u.x), eluf(u.y), eluf(u.z), eluf(u.w));
            }
        }
        *(float4*)&xs[row * 64 + c4 * 4] = v;
    }
    __syncthreads();

    int c  = t & 15;
    int rq = t >> 4;
    int j0 = c * 4;
    int rbase = rq * 4;

    ull acc01[4] = {0ull, 0ull, 0ull, 0ull};
    ull acc23[4] = {0ull, 0ull, 0ull, 0ull};

    #pragma unroll 8
    for (int k = 0; k < 64; k++) {
        float x0 = xs[(rbase + 0) * 64 + k];     // broadcast loads
        float x1 = xs[(rbase + 1) * 64 + k];
        float x2 = xs[(rbase + 2) * 64 + k];
        float x3 = xs[(rbase + 3) * 64 + k];
        ull xp01, xp23;
        PACK2(xp01, x0, x1);
        PACK2(xp23, x2, x3);
        ulonglong2 w01 = *(const ulonglong2*)&Wd[k * 128 + j0 * 2];      // {w0,w0},{w1,w1}
        ulonglong2 w23 = *(const ulonglong2*)&Wd[k * 128 + j0 * 2 + 4];  // {w2,w2},{w3,w3}
        FMA2(acc01[0], xp01, w01.x); FMA2(acc23[0], xp23, w01.x);
        FMA2(acc01[1], xp01, w01.y); FMA2(acc23[1], xp23, w01.y);
        FMA2(acc01[2], xp01, w23.x); FMA2(acc23[2], xp23, w23.x);
        FMA2(acc01[3], xp01, w23.y); FMA2(acc23[3], xp23, w23.y);
    }

    // unpack to per-row float4s
    float2 c01[4], c23[4];
    #pragma unroll
    for (int q = 0; q < 4; q++) {
        UNPACK2(c01[q].x, c01[q].y, acc01[q]);
        UNPACK2(c23[q].x, c23[q].y, acc23[q]);
    }
    float4 accs[4];
    accs[0] = make_float4(c01[0].x, c01[1].x, c01[2].x, c01[3].x);
    accs[1] = make_float4(c01[0].y, c01[1].y, c01[2].y, c01[3].y);
    accs[2] = make_float4(c23[0].x, c23[1].x, c23[2].x, c23[3].x);
    accs[3] = make_float4(c23[0].y, c23[1].y, c23[2].y, c23[3].y);

    float4 asv = *(const float4*)(a_s + j0);
    float4 adv = *(const float4*)(a_d + j0);

    #pragma unroll
    for (int i = 0; i < 4; i++) {
        int row = base + rbase + i;
        float4 a = accs[i];
        if (row < NNODES) {
            __half2 p0 = __floats2half2_rn(a.x, a.y);
            __half2 p1 = __floats2half2_rn(a.z, a.w);
            uint2 pk;
            pk.x = *(unsigned*)&p0;
            pk.y = *(unsigned*)&p1;
            *(uint2*)&g_h16[row * 32 + c * 2] = pk;
        }
        float ps = a.x * asv.x + a.y * asv.y + a.z * asv.z + a.w * asv.w;
        float pd = a.x * adv.x + a.y * adv.y + a.z * adv.z + a.w * adv.w;
        #pragma unroll
        for (int off = 8; off; off >>= 1) {
            ps += __shfl_xor_sync(0xffffffffu, ps, off);
            pd += __shfl_xor_sync(0xffffffffu, pd, off);
        }
        if (c == 0 && row < NNODES) {
            g_als[row] = ps;
            g_ald[row] = pd;
        }
    }
}

// ---------------- fused conv: 8 lanes per edge, LDG.128 gather -------------
__global__ __launch_bounds__(256) void k_conv(const float* __restrict__ bias) {
    const unsigned FULL = 0xffffffffu;
    int wid  = (blockIdx.x * 256 + threadIdx.x) >> 5;
    int lane = threadIdx.x & 31;
    if (wid >= NNODES) return;
    int grp = lane >> 3;      // 0..3: which edge of the quad
    int wi8 = lane & 7;       // feature slice: halves wi8*8 .. wi8*8+7

    int cnt = g_cursor[wid];
    cnt = cnt < CAP ? cnt : CAP;
    int r0 = wid * CAP;
    int r1 = r0 + cnt;
    float ald_d = g_ald[wid];

    float2 a0 = make_float2(0.f, 0.f), a1 = a0, a2 = a0, a3 = a0;
    float denp = 0.f;

    for (int cb = r0; cb < r1; cb += 32) {
        int e = cb + lane;
        int   s  = 0;
        float ex = 0.f;
        if (e < r1) {
            s = g_bucket[e];
            float sc = g_als[s] + ald_d;
            sc = sc > 0.f ? sc : 0.2f * sc;       // leaky relu
            ex = __expf(fminf(sc, 75.f));         // overflow guard (never hit)
        }
        denp += ex;
        int cl = (r1 - cb) < 32 ? (r1 - cb) : 32;
        #pragma unroll 2
        for (int j = 0; j < cl; j += 4) {
            int jj = j + grp;                     // <= 31 always
            int   sj  = __shfl_sync(FULL, s, jj);
            float exj = __shfl_sync(FULL, ex, jj);
            uint4 pk = *(const uint4*)&g_h16[sj * 32 + wi8 * 4];
            float2 f0 = __half22float2(*(__half2*)&pk.x);
            float2 f1 = __half22float2(*(__half2*)&pk.y);
            float2 f2 = __half22float2(*(__half2*)&pk.z);
            float2 f3 = __half22float2(*(__half2*)&pk.w);
            a0.x += exj * f0.x; a0.y += exj * f0.y;
            a1.x += exj * f1.x; a1.y += exj * f1.y;
            a2.x += exj * f2.x; a2.y += exj * f2.y;
            a3.x += exj * f3.x; a3.y += exj * f3.y;
        }
    }

    // merge the 4 edge-groups (same feature slice, disjoint edges)
    #pragma unroll
    for (int off = 8; off <= 16; off <<= 1) {
        a0.x += __shfl_xor_sync(FULL, a0.x, off);
        a0.y += __shfl_xor_sync(FULL, a0.y, off);
        a1.x += __shfl_xor_sync(FULL, a1.x, off);
        a1.y += __shfl_xor_sync(FULL, a1.y, off);
        a2.x += __shfl_xor_sync(FULL, a2.x, off);
        a2.y += __shfl_xor_sync(FULL, a2.y, off);
        a3.x += __shfl_xor_sync(FULL, a3.x, off);
        a3.y += __shfl_xor_sync(FULL, a3.y, off);
    }

    float den = denp;
    #pragma unroll
    for (int off = 16; off; off >>= 1)
        den += __shfl_xor_sync(FULL, den, off);

    if (grp == 0) {
        float inv = 1.f / den;
        float4 bv0 = *(const float4*)(bias + wi8 * 8);
        float4 bv1 = *(const float4*)(bias + wi8 * 8 + 4);
        float4 o0, o1;
        o0.x = a0.x * inv + bv0.x; o0.y = a0.y * inv + bv0.y;
        o0.z = a1.x * inv + bv0.z; o0.w = a1.y * inv + bv0.w;
        o1.x = a2.x * inv + bv1.x; o1.y = a2.y * inv + bv1.y;
        o1.z = a3.x * inv + bv1.z; o1.w = a3.y * inv + bv1.w;
        *(float4*)&g_abuf[wid * 64 + wi8 * 8]     = o0;
        *(float4*)&g_abuf[wid * 64 + wi8 * 8 + 4] = o1;
    }
}

// ---------------- MLP head + global_add_pool (f32x2 packed FMA) ------------
__global__ __launch_bounds__(256) void k_mlp_pool(
    const float* __restrict__ mw1, const float* __restrict__ mb1,
    const float* __restrict__ mw2, const float* __restrict__ mb2,
    const int* __restrict__ batch, float* __restrict__ out)
{
    __shared__ __align__(16) float W1s[64 * 68];
    __shared__ float W2s[64 * 12];
    __shared__ float b1s[64];
    __shared__ float b2s[NCLS];

    int t = threadIdx.x;
    for (int i = t; i < 64 * 64; i += 256)
        W1s[(i >> 6) * 68 + (i & 63)] = mw1[i];
    for (int i = t; i < 64 * NCLS; i += 256)
        W2s[(i / NCLS) * 12 + (i % NCLS)] = mw2[i];
    if (t < 64)   b1s[t] = mb1[t];
    if (t < NCLS) b2s[t] = mb2[t];
    __syncthreads();

    int node = blockIdx.x * blockDim.x + t;
    bool valid = node < NNODES;

    ull z2[32];
    #pragma unroll
    for (int m = 0; m < 32; m++) z2[m] = 0ull;

    int b = 0;
    if (valid) {
        b = batch[node];
        #pragma unroll
        for (int k4 = 0; k4 < 16; k4++) {
            float4 xv4 = *(const float4*)&g_abuf[node * 64 + k4 * 4];
            float xv[4] = {xv4.x, xv4.y, xv4.z, xv4.w};
            #pragma unroll
            for (int kk = 0; kk < 4; kk++) {
                float xk = eluf(xv[kk]);
                int k = k4 * 4 + kk;
                ull xkp;
                PACKDUP(xkp, xk);
                #pragma unroll
                for (int j2 = 0; j2 < 8; j2++) {   // 8 cols per iter (broadcast LDS.128)
                    ulonglong2 wp = *(const ulonglong2*)&W1s[k * 68 + j2 * 8];
                    FMA2(z2[j2 * 4 + 0], xkp, wp.x);
                    FMA2(z2[j2 * 4 + 1], xkp, wp.y);
                    ulonglong2 wq = *(const ulonglong2*)&W1s[k * 68 + j2 * 8 + 4];
                    FMA2(z2[j2 * 4 + 2], xkp, wq.x);
                    FMA2(z2[j2 * 4 + 3], xkp, wq.y);
                }
            }
        }
    }

    float y[NCLS];
    #pragma unroll
    for (int c2 = 0; c2 < NCLS; c2++) y[c2] = valid ? b2s[c2] : 0.f;

    if (valid) {
        #pragma unroll
        for (int m = 0; m < 32; m++) {
            float zl, zh;
            UNPACK2(zl, zh, z2[m]);
            float zj0 = zl + b1s[2 * m];
            float zj1 = zh + b1s[2 * m + 1];
            zj0 = zj0 > 0.f ? zj0 : 0.f;
            zj1 = zj1 > 0.f ? zj1 : 0.f;
            #pragma unroll
            for (int c2 = 0; c2 < NCLS; c2++) {
                y[c2] += zj0 * W2s[(2 * m) * 12 + c2];
                y[c2] += zj1 * W2s[(2 * m + 1) * 12 + c2];
            }
        }
    }

    unsigned mask = 0xffffffffu;
    int b0 = __shfl_sync(mask, b, 0);
    bool uni = __all_sync(mask, valid && (b == b0));
    if (uni) {
        #pragma unroll
        for (int c2 = 0; c2 < NCLS; c2++) {
            float v = y[c2];
            #pragma unroll
            for (int off = 16; off; off >>= 1)
                v += __shfl_xor_sync(mask, v, off);
            if ((t & 31) == 0) atomicAdd(&out[b0 * NCLS + c2], v);
        }
    } else if (valid) {
        #pragma unroll
        for (int c2 = 0; c2 < NCLS; c2++)
            atomicAdd(&out[b * NCLS + c2], y[c2]);
    }
}

// ---------------- launch ---------------------------------------------------
extern "C" void kernel_launch(void* const* d_in, const int* in_sizes, int n_in,
                              void* d_out, int out_size) {
    const float* x     = (const float*)d_in[0];
    const int*   ei    = (const int*)d_in[1];     // int32
    const int*   batch = (const int*)d_in[2];     // int32
    const float* W1  = (const float*)d_in[3];
    const float* as1 = (const float*)d_in[4];
    const float* ad1 = (const float*)d_in[5];
    const float* b1  = (const float*)d_in[6];
    const float* W2  = (const float*)d_in[7];
    const float* as2 = (const float*)d_in[8];
    const float* ad2 = (const float*)d_in[9];
    const float* b2  = (const float*)d_in[10];
    const float* mw1 = (const float*)d_in[11];
    const float* mb1 = (const float*)d_in[12];
    const float* mw2 = (const float*)d_in[13];
    const float* mb2 = (const float*)d_in[14];
    float* out = (float*)d_out;

    static cudaStream_t s2 = nullptr;
    static cudaEvent_t  eF = nullptr, eJ = nullptr;
    if (!s2) {
        cudaStreamCreateWithFlags(&s2, cudaStreamNonBlocking);
        cudaEventCreateWithFlags(&eF, cudaEventDisableTiming);
        cudaEventCreateWithFlags(&eJ, cudaEventDisableTiming);
    }

    const int TB = 256;
    int gridE4 = (NEDGES / 4 + TB - 1) / TB;      // NEDGES % 4 == 0
    int gridN  = (NNODES + TB - 1) / TB;
    int gridG  = (NNODES + 63) / 64;
    int gridC  = (NNODES * 32 + TB - 1) / TB;     // warp per node

    // fork: side stream runs GEMM-1 while stream 0 builds buckets
    cudaEventRecord(eF, 0);
    cudaStreamWaitEvent(s2, eF, 0);

    // stream 0: bucket build (no deg pass, no scan)
    k_init<<<gridN, TB>>>(out);
    k_scatter<<<gridE4, TB>>>(ei);

    // side stream: GEMM-1 (independent of buckets)
    k_gemm_attn<0><<<gridG, TB, 0, s2>>>(x, W1, as1, ad1);

    // join
    cudaEventRecord(eJ, s2);
    cudaStreamWaitEvent(0, eJ, 0);

    // conv 1
    k_conv<<<gridC, TB>>>(b1);

    // conv 2
    k_gemm_attn<1><<<gridG, TB>>>(nullptr, W2, as2, ad2);
    k_conv<<<gridC, TB>>>(b2);

    // MLP + pool
    k_mlp_pool<<<gridN, TB>>>(mw1, mb1, mw2, mb2, batch, out);
}

// round 14
// speedup vs baseline: 1.2326x; 1.2326x over previous
#include <cuda_runtime.h>
#include <cuda_fp16.h>
#include <math_constants.h>

#define NNODES 100000
#define NEDGES 1600000
#define HD     64
#define NCLS   10
#define NGRAPH 128
#define CAP    64     // bucket capacity per node (deg ~ Poisson(16); P(>63) ~ 1e-21)

// ---------------- scratch (device globals; no allocations) ----------------
__device__ __align__(16) __half2 g_h16[NNODES * 32];  // h rows, fp16 payload (128B/row)
__device__ __align__(16) float g_abuf[NNODES * HD];   // conv input / output (fp32)
__device__ float g_als[NNODES];
__device__ float g_ald[NNODES];
__device__ int   g_cursor[NNODES];                    // row length after scatter
__device__ int   g_bucket[NNODES * CAP];              // src ids, row n at n*CAP

__device__ __forceinline__ float eluf(float x) {
    return x > 0.f ? x : expm1f(x);
}

// ---------------- bucket init + out zero -----------------------------------
__global__ void k_init(float* __restrict__ out) {
    int i = blockIdx.x * blockDim.x + threadIdx.x;
    if (i < NNODES) {
        g_cursor[i] = 1;               // slot 0 = self loop
        g_bucket[i * CAP] = i;
    }
    if (i < NGRAPH * NCLS) out[i] = 0.f;
}

// ---------------- edge scatter into fixed buckets ---------------------------
// edge_index is INT32 (JAX x64 disabled downgrades jnp.int64 -> int32)
__global__ void k_scatter(const int* __restrict__ ei) {
    int i = (blockIdx.x * blockDim.x + threadIdx.x) * 4;
    if (i >= NEDGES) return;
    int4 s = *(const int4*)(ei + i);
    int4 d = *(const int4*)(ei + NEDGES + i);
    int p0 = atomicAdd(&g_cursor[d.x], 1);
    int p1 = atomicAdd(&g_cursor[d.y], 1);
    int p2 = atomicAdd(&g_cursor[d.z], 1);
    int p3 = atomicAdd(&g_cursor[d.w], 1);
    if (p0 < CAP) g_bucket[d.x * CAP + p0] = s.x;
    if (p1 < CAP) g_bucket[d.y * CAP + p1] = s.y;
    if (p2 < CAP) g_bucket[d.z * CAP + p2] = s.z;
    if (p3 < CAP) g_bucket[d.w * CAP + p3] = s.w;
}

// ---------------- GEMM + attention coefs (register-blocked 4x4) ------------
template <int LAYER>
__global__ __launch_bounds__(256) void k_gemm_attn(
    const float* __restrict__ xin,
    const float* __restrict__ W,
    const float* __restrict__ a_s,
    const float* __restrict__ a_d)
{
    __shared__ __align__(16) float Ws[64 * 68];
    __shared__ __align__(16) float xs[64 * 68];

    int t = threadIdx.x;
    int base = blockIdx.x * 64;

    for (int i = t; i < 1024; i += 256) {
        float4 w = *(const float4*)(W + i * 4);
        *(float4*)&Ws[(i >> 4) * 68 + (i & 15) * 4] = w;
    }
    for (int i = t; i < 1024; i += 256) {
        int row = i >> 4, c4 = i & 15;
        int grow = base + row;
        float4 v = make_float4(0.f, 0.f, 0.f, 0.f);
        if (grow < NNODES) {
            if (LAYER == 0) {
                v = *(const float4*)(xin + grow * 64 + c4 * 4);
            } else {
                float4 u = *(const float4*)&g_abuf[grow * 64 + c4 * 4];
                v = make_float4(eluf(u.x), eluf(u.y), eluf(u.z), eluf(u.w));
            }
        }
        *(float4*)&xs[row * 68 + c4 * 4] = v;
    }
    __syncthreads();

    int c  = t & 15;
    int rq = t >> 4;
    int j0 = c * 4;
    int rbase = rq * 4;

    float4 acc0 = make_float4(0.f,0.f,0.f,0.f);
    float4 acc1 = acc0, acc2 = acc0, acc3 = acc0;

    #pragma unroll 8
    for (int k = 0; k < 64; k++) {
        float4 w  = *(const float4*)&Ws[k * 68 + j0];
        float x0 = xs[(rbase + 0) * 68 + k];
        float x1 = xs[(rbase + 1) * 68 + k];
        float x2 = xs[(rbase + 2) * 68 + k];
        float x3 = xs[(rbase + 3) * 68 + k];
        acc0.x += x0 * w.x; acc0.y += x0 * w.y; acc0.z += x0 * w.z; acc0.w += x0 * w.w;
        acc1.x += x1 * w.x; acc1.y += x1 * w.y; acc1.z += x1 * w.z; acc1.w += x1 * w.w;
        acc2.x += x2 * w.x; acc2.y += x2 * w.y; acc2.z += x2 * w.z; acc2.w += x2 * w.w;
        acc3.x += x3 * w.x; acc3.y += x3 * w.y; acc3.z += x3 * w.z; acc3.w += x3 * w.w;
    }

    float4 asv = *(const float4*)(a_s + j0);
    float4 adv = *(const float4*)(a_d + j0);

    float4 accs[4] = {acc0, acc1, acc2, acc3};
    #pragma unroll
    for (int i = 0; i < 4; i++) {
        int row = base + rbase + i;
        float4 a = accs[i];
        if (row < NNODES) {
            __half2 p0 = __floats2half2_rn(a.x, a.y);
            __half2 p1 = __floats2half2_rn(a.z, a.w);
            uint2 pk;
            pk.x = *(unsigned*)&p0;
            pk.y = *(unsigned*)&p1;
            *(uint2*)&g_h16[row * 32 + c * 2] = pk;
        }
        float ps = a.x * asv.x + a.y * asv.y + a.z * asv.z + a.w * asv.w;
        float pd = a.x * adv.x + a.y * adv.y + a.z * adv.z + a.w * adv.w;
        #pragma unroll
        for (int off = 8; off; off >>= 1) {
            ps += __shfl_xor_sync(0xffffffffu, ps, off);
            pd += __shfl_xor_sync(0xffffffffu, pd, off);
        }
        if (c == 0 && row < NNODES) {
            g_als[row] = ps;
            g_ald[row] = pd;
        }
    }
}

// ---------------- fused conv: 8 lanes per edge, LDG.128 gather -------------
__global__ __launch_bounds__(256) void k_conv(const float* __restrict__ bias) {
    const unsigned FULL = 0xffffffffu;
    int wid  = (blockIdx.x * 256 + threadIdx.x) >> 5;
    int lane = threadIdx.x & 31;
    if (wid >= NNODES) return;
    int grp = lane >> 3;      // 0..3: which edge of the quad
    int wi8 = lane & 7;       // feature slice: halves wi8*8 .. wi8*8+7

    int cnt = g_cursor[wid];
    cnt = cnt < CAP ? cnt : CAP;
    int r0 = wid * CAP;
    int r1 = r0 + cnt;
    float ald_d = g_ald[wid];

    float2 a0 = make_float2(0.f, 0.f), a1 = a0, a2 = a0, a3 = a0;
    float denp = 0.f;

    for (int cb = r0; cb < r1; cb += 32) {
        int e = cb + lane;
        int   s  = 0;
        float ex = 0.f;
        if (e < r1) {
            s = g_bucket[e];
            float sc = g_als[s] + ald_d;
            sc = sc > 0.f ? sc : 0.2f * sc;       // leaky relu
            ex = __expf(fminf(sc, 75.f));         // overflow guard (never hit)
        }
        denp += ex;
        int cl = (r1 - cb) < 32 ? (r1 - cb) : 32;
        #pragma unroll 2
        for (int j = 0; j < cl; j += 4) {
            int jj = j + grp;                     // <= 31 always
            int   sj  = __shfl_sync(FULL, s, jj);
            float exj = __shfl_sync(FULL, ex, jj);
            uint4 pk = *(const uint4*)&g_h16[sj * 32 + wi8 * 4];
            float2 f0 = __half22float2(*(__half2*)&pk.x);
            float2 f1 = __half22float2(*(__half2*)&pk.y);
            float2 f2 = __half22float2(*(__half2*)&pk.z);
            float2 f3 = __half22float2(*(__half2*)&pk.w);
            a0.x += exj * f0.x; a0.y += exj * f0.y;
            a1.x += exj * f1.x; a1.y += exj * f1.y;
            a2.x += exj * f2.x; a2.y += exj * f2.y;
            a3.x += exj * f3.x; a3.y += exj * f3.y;
        }
    }

    // merge the 4 edge-groups (same feature slice, disjoint edges)
    #pragma unroll
    for (int off = 8; off <= 16; off <<= 1) {
        a0.x += __shfl_xor_sync(FULL, a0.x, off);
        a0.y += __shfl_xor_sync(FULL, a0.y, off);
        a1.x += __shfl_xor_sync(FULL, a1.x, off);
        a1.y += __shfl_xor_sync(FULL, a1.y, off);
        a2.x += __shfl_xor_sync(FULL, a2.x, off);
        a2.y += __shfl_xor_sync(FULL, a2.y, off);
        a3.x += __shfl_xor_sync(FULL, a3.x, off);
        a3.y += __shfl_xor_sync(FULL, a3.y, off);
    }

    float den = denp;
    #pragma unroll
    for (int off = 16; off; off >>= 1)
        den += __shfl_xor_sync(FULL, den, off);

    if (grp == 0) {
        float inv = 1.f / den;
        float4 bv0 = *(const float4*)(bias + wi8 * 8);
        float4 bv1 = *(const float4*)(bias + wi8 * 8 + 4);
        float4 o0, o1;
        o0.x = a0.x * inv + bv0.x; o0.y = a0.y * inv + bv0.y;
        o0.z = a1.x * inv + bv0.z; o0.w = a1.y * inv + bv0.w;
        o1.x = a2.x * inv + bv1.x; o1.y = a2.y * inv + bv1.y;
        o1.z = a3.x * inv + bv1.z; o1.w = a3.y * inv + bv1.w;
        *(float4*)&g_abuf[wid * 64 + wi8 * 8]     = o0;
        *(float4*)&g_abuf[wid * 64 + wi8 * 8 + 4] = o1;
    }
}

// ---------------- MLP head + global_add_pool (j-split, low regs) -----------
// Hidden layer computed in two 32-column halves: z[32] live at a time
// (~65 regs vs ~110 with z[64]) -> 2x resident blocks, better latency hiding.
// x row is reloaded + re-ELU'd per half (L2-resident; ~5% extra issues).
__global__ __launch_bounds__(256) void k_mlp_pool(
    const float* __restrict__ mw1, const float* __restrict__ mb1,
    const float* __restrict__ mw2, const float* __restrict__ mb2,
    const int* __restrict__ batch, float* __restrict__ out)
{
    __shared__ __align__(16) float W1s[64 * 68];
    __shared__ float W2s[64 * 12];
    __shared__ float b1s[64];
    __shared__ float b2s[NCLS];

    int t = threadIdx.x;
    for (int i = t; i < 64 * 64; i += 256)
        W1s[(i >> 6) * 68 + (i & 63)] = mw1[i];
    for (int i = t; i < 64 * NCLS; i += 256)
        W2s[(i / NCLS) * 12 + (i % NCLS)] = mw2[i];
    if (t < 64)   b1s[t] = mb1[t];
    if (t < NCLS) b2s[t] = mb2[t];
    __syncthreads();

    int node = blockIdx.x * blockDim.x + t;
    bool valid = node < NNODES;

    int b = valid ? batch[node] : 0;

    float y[NCLS];
    #pragma unroll
    for (int c2 = 0; c2 < NCLS; c2++) y[c2] = valid ? b2s[c2] : 0.f;

    #pragma unroll
    for (int half = 0; half < 2; half++) {
        int jbase = half * 32;
        float z[32];
        #pragma unroll
        for (int j = 0; j < 32; j++) z[j] = 0.f;

        if (valid) {
            #pragma unroll
            for (int k4 = 0; k4 < 16; k4++) {
                float4 xv4 = *(const float4*)&g_abuf[node * 64 + k4 * 4];
                float xv[4] = {xv4.x, xv4.y, xv4.z, xv4.w};
                #pragma unroll
                for (int kk = 0; kk < 4; kk++) {
                    float xk = eluf(xv[kk]);
                    int k = k4 * 4 + kk;
                    #pragma unroll
                    for (int j = 0; j < 32; j += 4) {
                        float4 w = *(const float4*)&W1s[k * 68 + jbase + j];
                        z[j]     += xk * w.x;
                        z[j + 1] += xk * w.y;
                        z[j + 2] += xk * w.z;
                        z[j + 3] += xk * w.w;
                    }
                }
            }
            #pragma unroll
            for (int j = 0; j < 32; j++) {
                float zj = z[j] + b1s[jbase + j];
                zj = zj > 0.f ? zj : 0.f;
                #pragma unroll
                for (int c2 = 0; c2 < NCLS; c2++)
                    y[c2] += zj * W2s[(jbase + j) * 12 + c2];
            }
        }
    }

    unsigned mask = 0xffffffffu;
    int b0 = __shfl_sync(mask, b, 0);
    bool uni = __all_sync(mask, valid && (b == b0));
    if (uni) {
        #pragma unroll
        for (int c2 = 0; c2 < NCLS; c2++) {
            float v = y[c2];
            #pragma unroll
            for (int off = 16; off; off >>= 1)
                v += __shfl_xor_sync(mask, v, off);
            if ((t & 31) == 0) atomicAdd(&out[b0 * NCLS + c2], v);
        }
    } else if (valid) {
        #pragma unroll
        for (int c2 = 0; c2 < NCLS; c2++)
            atomicAdd(&out[b * NCLS + c2], y[c2]);
    }
}

// ---------------- launch ---------------------------------------------------
extern "C" void kernel_launch(void* const* d_in, const int* in_sizes, int n_in,
                              void* d_out, int out_size) {
    const float* x     = (const float*)d_in[0];
    const int*   ei    = (const int*)d_in[1];     // int32
    const int*   batch = (const int*)d_in[2];     // int32
    const float* W1  = (const float*)d_in[3];
    const float* as1 = (const float*)d_in[4];
    const float* ad1 = (const float*)d_in[5];
    const float* b1  = (const float*)d_in[6];
    const float* W2  = (const float*)d_in[7];
    const float* as2 = (const float*)d_in[8];
    const float* ad2 = (const float*)d_in[9];
    const float* b2  = (const float*)d_in[10];
    const float* mw1 = (const float*)d_in[11];
    const float* mb1 = (const float*)d_in[12];
    const float* mw2 = (const float*)d_in[13];
    const float* mb2 = (const float*)d_in[14];
    float* out = (float*)d_out;

    static cudaStream_t s2 = nullptr;
    static cudaEvent_t  eF = nullptr, eJ = nullptr;
    if (!s2) {
        cudaStreamCreateWithFlags(&s2, cudaStreamNonBlocking);
        cudaEventCreateWithFlags(&eF, cudaEventDisableTiming);
        cudaEventCreateWithFlags(&eJ, cudaEventDisableTiming);
    }

    const int TB = 256;
    int gridE4 = (NEDGES / 4 + TB - 1) / TB;      // NEDGES % 4 == 0
    int gridN  = (NNODES + TB - 1) / TB;
    int gridG  = (NNODES + 63) / 64;
    int gridC  = (NNODES * 32 + TB - 1) / TB;     // warp per node

    // fork: side stream runs GEMM-1 while stream 0 builds buckets
    cudaEventRecord(eF, 0);
    cudaStreamWaitEvent(s2, eF, 0);

    // stream 0: bucket build (no deg pass, no scan)
    k_init<<<gridN, TB>>>(out);
    k_scatter<<<gridE4, TB>>>(ei);

    // side stream: GEMM-1 (independent of buckets)
    k_gemm_attn<0><<<gridG, TB, 0, s2>>>(x, W1, as1, ad1);

    // join
    cudaEventRecord(eJ, s2);
    cudaStreamWaitEvent(0, eJ, 0);

    // conv 1
    k_conv<<<gridC, TB>>>(b1);

    // conv 2
    k_gemm_attn<1><<<gridG, TB>>>(nullptr, W2, as2, ad2);
    k_conv<<<gridC, TB>>>(b2);

    // MLP + pool
    k_mlp_pool<<<gridN, TB>>>(mw1, mb1, mw2, mb2, batch, out);
}